// round 3
// baseline (speedup 1.0000x reference)
#include <cuda_runtime.h>
#include <cuda_bf16.h>
#include <cstdint>

#define MARGIN 0.5f
#define POS_W 1.0f
#define NEG_W 1.0f

#define BLOCKS_PER_BATCH 8
#define R_THREADS 256
#define MAX_PARTIALS 8192
#define MAX_B 1024

// Scratch (allocations forbidden; __device__ globals).
// Every g_partial slot used is rewritten each call -> no zeroing needed.
__device__ float g_partial[MAX_PARTIALS];
__device__ unsigned int g_arrival = 0;   // last block resets to 0 each call

__global__ __launch_bounds__(R_THREADS) void fused_loss_kernel(
    const float* __restrict__ graph,
    const int* __restrict__ labels,
    float* __restrict__ out,
    int B, int ne_per_batch) {

    const int b = blockIdx.x / BLOCKS_PER_BATCH;
    const int chunk = blockIdx.x % BLOCKS_PER_BATCH;
    const int vec_per_batch = ne_per_batch >> 2;               // float4 count
    const int vec_per_chunk = vec_per_batch / BLOCKS_PER_BATCH;

    const float4* __restrict__ base =
        reinterpret_cast<const float4*>(graph) +
        (size_t)b * vec_per_batch + (size_t)chunk * vec_per_chunk;

    float acc = 0.0f;
    for (int i = threadIdx.x; i < vec_per_chunk; i += R_THREADS) {
        float4 v = base[i];
        acc += (v.x + v.y) + (v.z + v.w);
    }

    // block reduce
    #pragma unroll
    for (int off = 16; off > 0; off >>= 1)
        acc += __shfl_xor_sync(0xFFFFFFFFu, acc, off);

    __shared__ float warp_sums[R_THREADS / 32];
    const int lane = threadIdx.x & 31, wid = threadIdx.x >> 5;
    if (lane == 0) warp_sums[wid] = acc;
    __syncthreads();

    __shared__ bool is_last;
    if (wid == 0) {
        float s = (lane < R_THREADS / 32) ? warp_sums[lane] : 0.0f;
        #pragma unroll
        for (int off = 4; off > 0; off >>= 1)
            s += __shfl_xor_sync(0xFFFFFFFFu, s, off);
        if (lane == 0) {
            g_partial[blockIdx.x] = s;
            __threadfence();
            unsigned int prev = atomicAdd(&g_arrival, 1u);
            is_last = (prev == gridDim.x - 1);
        }
    }
    __syncthreads();

    if (!is_last) return;

    // ---- tail: last block computes pooled sims + pair loss ----
    if (threadIdx.x == 0) g_arrival = 0;   // reset for next graph replay

    __shared__ float gs[MAX_B];
    __shared__ int lab[MAX_B];
    const float inv_ne = 1.0f / (float)ne_per_batch;

    for (int i = threadIdx.x; i < B; i += R_THREADS) {
        float s = 0.0f;
        #pragma unroll
        for (int c = 0; c < BLOCKS_PER_BATCH; ++c)
            s += g_partial[i * BLOCKS_PER_BATCH + c];
        gs[i] = s * inv_ne;
        lab[i] = labels[i];
    }
    __syncthreads();

    float pacc = 0.0f;
    for (int i = threadIdx.x; i < B; i += R_THREADS) {
        const float gi = gs[i];
        const int li = lab[i];
        for (int j = i + 1; j < B; ++j) {
            const float sim = gi * gs[j];
            const float pos = fmaxf(MARGIN - sim, 0.0f);
            const float neg = fmaxf(sim - (1.0f - MARGIN), 0.0f);
            pacc += (li == lab[j]) ? (POS_W * pos) : (NEG_W * neg);
        }
    }

    #pragma unroll
    for (int off = 16; off > 0; off >>= 1)
        pacc += __shfl_xor_sync(0xFFFFFFFFu, pacc, off);

    __shared__ float pw[R_THREADS / 32];
    if (lane == 0) pw[wid] = pacc;
    __syncthreads();

    if (wid == 0) {
        float s = (lane < R_THREADS / 32) ? pw[lane] : 0.0f;
        #pragma unroll
        for (int off = 4; off > 0; off >>= 1)
            s += __shfl_xor_sync(0xFFFFFFFFu, s, off);
        if (lane == 0) {
            const float num_pairs = 0.5f * (float)B * (float)(B - 1);
            out[0] = s / num_pairs;
        }
    }
}

extern "C" void kernel_launch(void* const* d_in, const int* in_sizes, int n_in,
                              void* d_out, int out_size) {
    const float* graph = (const float*)d_in[0];
    const int* labels = (const int*)d_in[1];
    float* out = (float*)d_out;

    const int total = in_sizes[0];   // B * N * N
    const int B = in_sizes[1];       // 256
    const int ne = total / B;        // N*N = 262144

    fused_loss_kernel<<<B * BLOCKS_PER_BATCH, R_THREADS>>>(graph, labels, out, B, ne);
}

// round 4
// speedup vs baseline: 1.0455x; 1.0455x over previous
#include <cuda_runtime.h>
#include <cuda_bf16.h>
#include <cstdint>

#define MARGIN 0.5f
#define POS_W 1.0f
#define NEG_W 1.0f

#define BLOCKS_PER_BATCH 4
#define R_THREADS 256
#define MAX_PARTIALS 8192
#define MAX_B 1024

// Scratch (allocations forbidden; __device__ globals).
// Every g_partial slot used is rewritten each call -> no zeroing needed.
__device__ float g_partial[MAX_PARTIALS];
__device__ unsigned int g_arrival = 0;   // last block resets to 0 each call

__global__ __launch_bounds__(R_THREADS, 8) void fused_loss_kernel(
    const float* __restrict__ graph,
    const int* __restrict__ labels,
    float* __restrict__ out,
    int B, int ne_per_batch) {

    const int b = blockIdx.x / BLOCKS_PER_BATCH;
    const int chunk = blockIdx.x % BLOCKS_PER_BATCH;
    const int vec_per_batch = ne_per_batch >> 2;               // float4 count
    const int vec_per_chunk = vec_per_batch / BLOCKS_PER_BATCH;

    const float4* __restrict__ base =
        reinterpret_cast<const float4*>(graph) +
        (size_t)b * vec_per_batch + (size_t)chunk * vec_per_chunk;

    // 4 independent accumulators, unroll-4: breaks the serial FADD chain and
    // lets ptxas front-batch 4 LDG.128s per iteration (higher MLP).
    float a0 = 0.0f, a1 = 0.0f, a2 = 0.0f, a3 = 0.0f;
    int i = threadIdx.x;
    const int stride = R_THREADS;
    const int n4 = vec_per_chunk & ~(4 * stride - 1);  // full unroll-4 span
    for (; i < n4; i += 4 * stride) {
        float4 v0 = base[i];
        float4 v1 = base[i + stride];
        float4 v2 = base[i + 2 * stride];
        float4 v3 = base[i + 3 * stride];
        a0 += (v0.x + v0.y) + (v0.z + v0.w);
        a1 += (v1.x + v1.y) + (v1.z + v1.w);
        a2 += (v2.x + v2.y) + (v2.z + v2.w);
        a3 += (v3.x + v3.y) + (v3.z + v3.w);
    }
    for (; i < vec_per_chunk; i += stride) {
        float4 v = base[i];
        a0 += (v.x + v.y) + (v.z + v.w);
    }
    float acc = (a0 + a1) + (a2 + a3);

    // block reduce
    #pragma unroll
    for (int off = 16; off > 0; off >>= 1)
        acc += __shfl_xor_sync(0xFFFFFFFFu, acc, off);

    __shared__ float warp_sums[R_THREADS / 32];
    const int lane = threadIdx.x & 31, wid = threadIdx.x >> 5;
    if (lane == 0) warp_sums[wid] = acc;
    __syncthreads();

    __shared__ bool is_last;
    if (wid == 0) {
        float s = (lane < R_THREADS / 32) ? warp_sums[lane] : 0.0f;
        #pragma unroll
        for (int off = 4; off > 0; off >>= 1)
            s += __shfl_xor_sync(0xFFFFFFFFu, s, off);
        if (lane == 0) {
            g_partial[blockIdx.x] = s;
            __threadfence();
            unsigned int prev = atomicAdd(&g_arrival, 1u);
            is_last = (prev == gridDim.x - 1);
        }
    }
    __syncthreads();

    if (!is_last) return;

    // ---- tail: last block computes pooled sims + pair loss ----
    if (threadIdx.x == 0) g_arrival = 0;   // reset for next graph replay

    __shared__ float gs[MAX_B];
    __shared__ int lab[MAX_B];
    const float inv_ne = 1.0f / (float)ne_per_batch;

    for (int t = threadIdx.x; t < B; t += R_THREADS) {
        float s = 0.0f;
        #pragma unroll
        for (int c = 0; c < BLOCKS_PER_BATCH; ++c)
            s += g_partial[t * BLOCKS_PER_BATCH + c];
        gs[t] = s * inv_ne;
        lab[t] = labels[t];
    }
    __syncthreads();

    float pacc = 0.0f;
    for (int t = threadIdx.x; t < B; t += R_THREADS) {
        const float gi = gs[t];
        const int li = lab[t];
        for (int j = t + 1; j < B; ++j) {
            const float sim = gi * gs[j];
            const float pos = fmaxf(MARGIN - sim, 0.0f);
            const float neg = fmaxf(sim - (1.0f - MARGIN), 0.0f);
            pacc += (li == lab[j]) ? (POS_W * pos) : (NEG_W * neg);
        }
    }

    #pragma unroll
    for (int off = 16; off > 0; off >>= 1)
        pacc += __shfl_xor_sync(0xFFFFFFFFu, pacc, off);

    __shared__ float pw[R_THREADS / 32];
    if (lane == 0) pw[wid] = pacc;
    __syncthreads();

    if (wid == 0) {
        float s = (lane < R_THREADS / 32) ? pw[lane] : 0.0f;
        #pragma unroll
        for (int off = 4; off > 0; off >>= 1)
            s += __shfl_xor_sync(0xFFFFFFFFu, s, off);
        if (lane == 0) {
            const float num_pairs = 0.5f * (float)B * (float)(B - 1);
            out[0] = s / num_pairs;
        }
    }
}

extern "C" void kernel_launch(void* const* d_in, const int* in_sizes, int n_in,
                              void* d_out, int out_size) {
    const float* graph = (const float*)d_in[0];
    const int* labels = (const int*)d_in[1];
    float* out = (float*)d_out;

    const int total = in_sizes[0];   // B * N * N
    const int B = in_sizes[1];       // 256
    const int ne = total / B;        // N*N = 262144

    fused_loss_kernel<<<B * BLOCKS_PER_BATCH, R_THREADS>>>(graph, labels, out, B, ne);
}